// round 15
// baseline (speedup 1.0000x reference)
#include <cuda_runtime.h>
#include <cuda_fp16.h>
#include <cstdint>

#define S_LEN   2048
#define D_MODEL 1024
#define NH      16
#define DKH     64
#define BATCH   2
#define M_TOTAL (BATCH * S_LEN)   // 4096

// fp16 scratch
__device__ __half g_xh[M_TOTAL * D_MODEL];
__device__ __half g_wt[4 * D_MODEL * D_MODEL];   // [z][N][K] (transposed)
__device__ __half g_q [BATCH * NH * S_LEN * DKH];
__device__ __half g_k [BATCH * NH * S_LEN * DKH];
__device__ __half g_v [BATCH * NH * S_LEN * DKH];
__device__ __half g_ao[M_TOTAL * D_MODEL];

__device__ __forceinline__ uint32_t smem_u32(const void* p) {
    uint32_t a;
    asm("{ .reg .u64 t; cvta.to.shared.u64 t, %1; cvt.u32.u64 %0, t; }" : "=r"(a) : "l"(p));
    return a;
}
__device__ __forceinline__ void cp16(uint32_t dst, const void* src) {
    asm volatile("cp.async.cg.shared.global [%0], [%1], 16;" :: "r"(dst), "l"(src));
}
#define CP_COMMIT() asm volatile("cp.async.commit_group;" ::: "memory")
#define CP_WAIT(n)  asm volatile("cp.async.wait_group %0;" :: "n"(n) : "memory")

__device__ __forceinline__ void ldsm4(uint32_t& r0, uint32_t& r1, uint32_t& r2,
                                      uint32_t& r3, uint32_t addr) {
    asm volatile("ldmatrix.sync.aligned.m8n8.x4.shared.b16 {%0,%1,%2,%3}, [%4];"
                 : "=r"(r0), "=r"(r1), "=r"(r2), "=r"(r3) : "r"(addr));
}
__device__ __forceinline__ void ldsm4t(uint32_t& r0, uint32_t& r1, uint32_t& r2,
                                       uint32_t& r3, uint32_t addr) {
    asm volatile("ldmatrix.sync.aligned.m8n8.x4.trans.shared.b16 {%0,%1,%2,%3}, [%4];"
                 : "=r"(r0), "=r"(r1), "=r"(r2), "=r"(r3) : "r"(addr));
}
__device__ __forceinline__ void mma_f16(float c[4], const uint32_t a[4],
                                        uint32_t b0, uint32_t b1) {
    asm volatile(
        "mma.sync.aligned.m16n8k16.row.col.f32.f16.f16.f32 "
        "{%0,%1,%2,%3}, {%4,%5,%6,%7}, {%8,%9}, {%0,%1,%2,%3};"
        : "+f"(c[0]), "+f"(c[1]), "+f"(c[2]), "+f"(c[3])
        : "r"(a[0]), "r"(a[1]), "r"(a[2]), "r"(a[3]), "r"(b0), "r"(b1));
}
__device__ __forceinline__ uint32_t h2pack(float lo, float hi) {
    __half2 h = __floats2half2_rn(lo, hi);
    return *(uint32_t*)&h;
}

// ============================================================================
// Prep: x -> fp16 (same layout); W -> fp16 transposed [N][K].
// ============================================================================
__global__ __launch_bounds__(256)
void prep_kernel(const float* __restrict__ x,
                 const float* __restrict__ Wq, const float* __restrict__ Wk,
                 const float* __restrict__ Wv, const float* __restrict__ Wo,
                 __half* __restrict__ xh, __half* __restrict__ wt) {
    if (blockIdx.z == 0) {
        const int n4 = M_TOTAL * D_MODEL / 4;
        int bid = blockIdx.y * gridDim.x + blockIdx.x;
        for (int i = bid * 256 + threadIdx.x; i < n4; i += gridDim.x * gridDim.y * 256) {
            float4 v = ((const float4*)x)[i];
            __half2 h01 = __floats2half2_rn(v.x, v.y);
            __half2 h23 = __floats2half2_rn(v.z, v.w);
            uint2 u = {*(uint32_t*)&h01, *(uint32_t*)&h23};
            ((uint2*)xh)[i] = u;
        }
        return;
    }
    __shared__ float tile[32][33];
    const float* W = blockIdx.z == 1 ? Wq : blockIdx.z == 2 ? Wk
                   : blockIdx.z == 3 ? Wv : Wo;
    __half* o = wt + (size_t)(blockIdx.z - 1) * D_MODEL * D_MODEL;
    int bx = blockIdx.x * 32, by = blockIdx.y * 32;
    int tx = threadIdx.x & 31, ty = threadIdx.x >> 5;
#pragma unroll
    for (int j = 0; j < 4; j++)
        tile[ty + 8 * j][tx] = W[(size_t)(bx + ty + 8 * j) * D_MODEL + by + tx];
    __syncthreads();
#pragma unroll
    for (int j = 0; j < 4; j++)
        o[(size_t)(by + ty + 8 * j) * D_MODEL + bx + tx] =
            __float2half_rn(tile[tx][ty + 8 * j]);
}

// ============================================================================
// fp16 HMMA GEMM: block tile 128x256 (24B fill per MMA, A re-reads halved),
// K-chunk 32, 8 warps (2x4 of 64x64), 256 threads, 1 CTA/SM, 4-stage ring,
// fills 2 ahead, ONE barrier per chunk.
// Fill: A = 128 rows x 4 chunks (2/thread), B = 256 rows x 4 chunks (4/thread).
// LAYOUT 0: f32 [M,N]; LAYOUT 1: fp16 [B,H,S,dk] scaled.
// ============================================================================
#define GAP32    40                        // padded halves per 32-half row
#define G_STG_B  ((128 + 256) * GAP32 * 2) // 30720 bytes (A 128 + B 256 rows)
#define G_NSTG   4
#define G_SMEM_B (G_NSTG * G_STG_B)        // 122880

template <int LAYOUT>
__device__ __forceinline__
void gemm_body(const __half* __restrict__ A, const __half* __restrict__ Wt,
               const float* __restrict__ bias, void* __restrict__ outv,
               float scale) {
    extern __shared__ char smraw[];
    const uint32_t sb = smem_u32(smraw);
    const int t    = threadIdx.x;
    const int lane = t & 31;
    const int warp = t >> 5;             // 0..7
    const int gid  = lane >> 2;
    const int tig  = lane & 3;
    const int wrow = warp >> 2;          // 0..1
    const int wcol = warp & 3;           // 0..3
    const int m0   = blockIdx.y * 128;
    const int n0   = blockIdx.x * 256;

    float acc[4][8][4];
#pragma unroll
    for (int i = 0; i < 4; i++)
#pragma unroll
        for (int j = 0; j < 8; j++)
#pragma unroll
            for (int k = 0; k < 4; k++) acc[i][j][k] = 0.f;

    auto fill = [&](int chunk, int st) {
        const int kb = chunk * 32;
        const uint32_t ab = sb + st * G_STG_B;
        const uint32_t bb = ab + 128 * GAP32 * 2;
        // A: 128 rows x 32 halves = 512 x 16B, 2 per thread
#pragma unroll
        for (int j = 0; j < 2; j++) {
            int lin = t + j * 256;
            int r = lin >> 2, c8 = (lin & 3) * 8;
            cp16(ab + (r * GAP32 + c8) * 2, &A[(size_t)(m0 + r) * D_MODEL + kb + c8]);
        }
        // B: 256 rows x 32 halves = 1024 x 16B, 4 per thread
#pragma unroll
        for (int j = 0; j < 4; j++) {
            int lin = t + j * 256;
            int r = lin >> 2, c8 = (lin & 3) * 8;
            cp16(bb + (r * GAP32 + c8) * 2, &Wt[(size_t)(n0 + r) * D_MODEL + kb + c8]);
        }
    };

    fill(0, 0); CP_COMMIT();
    fill(1, 1); CP_COMMIT();

    const int a_row8 = (lane & 7) + (((lane & 15) >> 3) << 3);
    const int a_kk8  = (lane >> 4) << 3;
    const int b_row8 = (lane & 7) + (((lane >> 4) & 1) << 3);
    const int b_kk8  = ((lane >> 3) & 1) << 3;

    for (int i = 0; i < 32; i++) {
        if (i + 2 < 32) fill(i + 2, (i + 2) & 3);
        CP_COMMIT();
        CP_WAIT(2);
        __syncthreads();
        const uint32_t ab = sb + (i & 3) * G_STG_B;
        const uint32_t bb = ab + 128 * GAP32 * 2;
#pragma unroll
        for (int kg = 0; kg < 2; kg++) {
            const int kk = kg * 16;
            uint32_t a[4][4];
#pragma unroll
            for (int mt = 0; mt < 4; mt++) {
                int R = wrow * 64 + mt * 16;
                ldsm4(a[mt][0], a[mt][1], a[mt][2], a[mt][3],
                      ab + ((R + a_row8) * GAP32 + kk + a_kk8) * 2);
            }
#pragma unroll
            for (int p = 0; p < 4; p++) {
                int N0 = wcol * 64 + p * 16;
                uint32_t b0, b1, b2, b3;
                ldsm4(b0, b1, b2, b3, bb + ((N0 + b_row8) * GAP32 + kk + b_kk8) * 2);
#pragma unroll
                for (int mt = 0; mt < 4; mt++) {
                    mma_f16(acc[mt][2 * p + 0], a[mt], b0, b1);
                    mma_f16(acc[mt][2 * p + 1], a[mt], b2, b3);
                }
            }
        }
        // no trailing barrier: 4-stage ring keeps writes 2 stages from reads
    }

#pragma unroll
    for (int mt = 0; mt < 4; mt++)
#pragma unroll
        for (int nt = 0; nt < 8; nt++) {
            int c0 = n0 + wcol * 64 + nt * 8 + tig * 2;
            float b0 = bias[c0], b1 = bias[c0 + 1];
#pragma unroll
            for (int h2 = 0; h2 < 2; h2++) {
                int r = m0 + wrow * 64 + mt * 16 + gid + 8 * h2;
                float v0 = acc[mt][nt][2 * h2 + 0] + b0;
                float v1 = acc[mt][nt][2 * h2 + 1] + b1;
                if (LAYOUT == 0) {
                    *(float2*)&((float*)outv)[(size_t)r * D_MODEL + c0] =
                        make_float2(v0, v1);
                } else {
                    int bb = r >> 11, ss = r & 2047;
                    int hh = c0 >> 6, dd = c0 & 63;
                    size_t idx = ((size_t)((bb * NH + hh) * S_LEN) + ss) * DKH + dd;
                    *(__half2*)&((__half*)outv)[idx] =
                        __floats2half2_rn(v0 * scale, v1 * scale);
                }
            }
        }
}

__global__ __launch_bounds__(256, 1)
void gemm_qkv_kernel(const __half* __restrict__ xh, const __half* __restrict__ wt,
                     const float* __restrict__ bq, const float* __restrict__ bk,
                     const float* __restrict__ bv,
                     __half* __restrict__ oq, __half* __restrict__ ok,
                     __half* __restrict__ ov) {
    const float* b; __half* o; float sc;
    const __half* W = wt + (size_t)blockIdx.z * D_MODEL * D_MODEL;
    if (blockIdx.z == 0)      { b = bq; o = oq; sc = 0.125f; }   // fold 1/sqrt(dk) into Q
    else if (blockIdx.z == 1) { b = bk; o = ok; sc = 1.f; }
    else                      { b = bv; o = ov; sc = 1.f; }
    gemm_body<1>(xh, W, b, o, sc);
}

__global__ __launch_bounds__(256, 1)
void gemm_out_kernel(const __half* __restrict__ A, const __half* __restrict__ wt,
                     const float* __restrict__ bias, float* __restrict__ out) {
    gemm_body<0>(A, wt + (size_t)3 * D_MODEL * D_MODEL, bias, out, 1.f);
}

// ============================================================================
// Flash attention (R12, current best): fp16 HMMA, max-free softmax, Q-tile
// 128, KV-tile 64, 4 warps / 128 threads, warp tile 32x64 (two m-tiles),
// 2 CTAs/SM, 4-stage single-barrier cp.async pipeline.
// ============================================================================
#define QT     128
#define KT     64
#define KVP    72
#define KV_STG (KT * KVP)                 // halves per stage: 4608
#define A_SMEM_B (8 * KV_STG * 2)         // 73728 bytes (4 K + 4 V stages)
#define N_KT   (S_LEN / KT)

__global__ __launch_bounds__(128, 2)
void attn_kernel(const __half* __restrict__ Q, const __half* __restrict__ K,
                 const __half* __restrict__ V, __half* __restrict__ AO) {
    extern __shared__ char smraw[];
    const uint32_t sb  = smem_u32(smraw);
    const uint32_t sbK = sb;
    const uint32_t sbV = sb + 4 * KV_STG * 2;

    const int t    = threadIdx.x;
    const int lane = t & 31;
    const int warp = t >> 5;            // 0..3
    const int gid  = lane >> 2;
    const int tig  = lane & 3;
    const int qt   = blockIdx.x;        // 0..15
    const int bh   = blockIdx.y;        // 0..31
    const int rA   = warp * 32 + gid;   // m-tile 0 rows: rA, rA+8; m-tile 1: +16,+24

    const __half* kg_ = K + (size_t)bh * S_LEN * DKH;
    const __half* vg  = V + (size_t)bh * S_LEN * DKH;

    // Q fragments for both m-tiles, loaded once from global
    uint32_t qf[2][4][4];
#pragma unroll
    for (int mt = 0; mt < 2; mt++) {
        const __half* q0 = Q + ((size_t)bh * S_LEN + qt * QT + rA + 16 * mt) * DKH;
        const __half* q1 = q0 + 8 * DKH;
#pragma unroll
        for (int kg = 0; kg < 4; kg++) {
            qf[mt][kg][0] = *(const uint32_t*)&q0[16 * kg + 2 * tig];
            qf[mt][kg][1] = *(const uint32_t*)&q1[16 * kg + 2 * tig];
            qf[mt][kg][2] = *(const uint32_t*)&q0[16 * kg + 8 + 2 * tig];
            qf[mt][kg][3] = *(const uint32_t*)&q1[16 * kg + 8 + 2 * tig];
        }
    }

    auto fillKV = [&](int kt, int s) {
        const __half* kt_ = kg_ + kt * KT * DKH;
        const __half* vt_ = vg  + kt * KT * DKH;
#pragma unroll
        for (int j = 0; j < 4; j++) {
            int lin = t + j * 128;
            int r = lin >> 3, c8 = (lin & 7) * 8;
            cp16(sbK + s * KV_STG * 2 + (r * KVP + c8) * 2, &kt_[r * DKH + c8]);
            cp16(sbV + s * KV_STG * 2 + (r * KVP + c8) * 2, &vt_[r * DKH + c8]);
        }
    };

    float o[2][8][4];
#pragma unroll
    for (int mt = 0; mt < 2; mt++)
#pragma unroll
        for (int i = 0; i < 8; i++)
#pragma unroll
            for (int j = 0; j < 4; j++) o[mt][i][j] = 0.f;
    float lr[2][2] = {{0.f, 0.f}, {0.f, 0.f}};   // per-thread partial sums

    const int kb_row8 = (lane & 7) + (((lane >> 4) & 1) << 3);
    const int kb_kk8  = ((lane >> 3) & 1) << 3;
    const int vb_row8 = (lane & 7) + (((lane >> 3) & 1) << 3);
    const int vb_cc8  = ((lane >> 4) & 1) << 3;

    fillKV(0, 0); CP_COMMIT();
    fillKV(1, 1); CP_COMMIT();

    for (int kt = 0; kt < N_KT; kt++) {
        if (kt + 2 < N_KT) fillKV(kt + 2, (kt + 2) & 3);
        CP_COMMIT();
        CP_WAIT(2);
        __syncthreads();
        const int st = kt & 3;
        const uint32_t Ks = sbK + st * KV_STG * 2;
        const uint32_t Vs = sbV + st * KV_STG * 2;

        float s[2][8][4];
#pragma unroll
        for (int mt = 0; mt < 2; mt++)
#pragma unroll
            for (int i = 0; i < 8; i++)
#pragma unroll
                for (int j = 0; j < 4; j++) s[mt][i][j] = 0.f;

        // S = Q @ K^T : each K fragment feeds 4 MMAs (2 m-tiles x 2 n-halves)
#pragma unroll
        for (int kg = 0; kg < 4; kg++) {
            const int kk = kg * 16;
#pragma unroll
            for (int p = 0; p < 4; p++) {
                uint32_t b0, b1, b2, b3;
                ldsm4(b0, b1, b2, b3,
                      Ks + ((p * 16 + kb_row8) * KVP + kk + kb_kk8) * 2);
#pragma unroll
                for (int mt = 0; mt < 2; mt++) {
                    mma_f16(s[mt][2 * p + 0], qf[mt][kg], b0, b1);
                    mma_f16(s[mt][2 * p + 1], qf[mt][kg], b2, b3);
                }
            }
        }

        // max-free softmax numerator; accumulate partial denominators
#pragma unroll
        for (int mt = 0; mt < 2; mt++)
#pragma unroll
            for (int nt = 0; nt < 8; nt++) {
                s[mt][nt][0] = __expf(s[mt][nt][0]);
                s[mt][nt][1] = __expf(s[mt][nt][1]);
                s[mt][nt][2] = __expf(s[mt][nt][2]);
                s[mt][nt][3] = __expf(s[mt][nt][3]);
                lr[mt][0] += s[mt][nt][0] + s[mt][nt][1];
                lr[mt][1] += s[mt][nt][2] + s[mt][nt][3];
            }

        // O += P @ V : each V fragment feeds 4 MMAs
#pragma unroll
        for (int kg = 0; kg < 4; kg++) {
            uint32_t pa[2][4];
#pragma unroll
            for (int mt = 0; mt < 2; mt++) {
                pa[mt][0] = h2pack(s[mt][2 * kg][0],     s[mt][2 * kg][1]);
                pa[mt][1] = h2pack(s[mt][2 * kg][2],     s[mt][2 * kg][3]);
                pa[mt][2] = h2pack(s[mt][2 * kg + 1][0], s[mt][2 * kg + 1][1]);
                pa[mt][3] = h2pack(s[mt][2 * kg + 1][2], s[mt][2 * kg + 1][3]);
            }
#pragma unroll
            for (int p = 0; p < 4; p++) {
                uint32_t v0, v1, v2, v3;
                ldsm4t(v0, v1, v2, v3,
                       Vs + ((kg * 16 + vb_row8) * KVP + p * 16 + vb_cc8) * 2);
#pragma unroll
                for (int mt = 0; mt < 2; mt++) {
                    mma_f16(o[mt][2 * p + 0], pa[mt], v0, v1);
                    mma_f16(o[mt][2 * p + 1], pa[mt], v2, v3);
                }
            }
        }
        // no trailing barrier: 4-stage ring
    }

    // reduce denominators across the 4 threads of each row group, write out
    int bb = bh >> 4, hh = bh & 15;
#pragma unroll
    for (int mt = 0; mt < 2; mt++) {
        float l0 = lr[mt][0], l1 = lr[mt][1];
        l0 += __shfl_xor_sync(0xffffffffu, l0, 1);
        l0 += __shfl_xor_sync(0xffffffffu, l0, 2);
        l1 += __shfl_xor_sync(0xffffffffu, l1, 1);
        l1 += __shfl_xor_sync(0xffffffffu, l1, 2);
        float il0 = 1.f / l0, il1 = 1.f / l1;
        int q0 = qt * QT + rA + 16 * mt;
        size_t base0 = ((size_t)(bb * S_LEN + q0)) * D_MODEL + hh * DKH;
        size_t base1 = base0 + (size_t)8 * D_MODEL;
#pragma unroll
        for (int nt = 0; nt < 8; nt++) {
            int dd = nt * 8 + tig * 2;
            *(__half2*)&AO[base0 + dd] =
                __floats2half2_rn(o[mt][nt][0] * il0, o[mt][nt][1] * il0);
            *(__half2*)&AO[base1 + dd] =
                __floats2half2_rn(o[mt][nt][2] * il1, o[mt][nt][3] * il1);
        }
    }
}

// ============================================================================
extern "C" void kernel_launch(void* const* d_in, const int* in_sizes, int n_in,
                              void* d_out, int out_size) {
    (void)in_sizes; (void)n_in; (void)out_size;
    const float* x  = (const float*)d_in[0];
    const float* Wq = (const float*)d_in[1];
    const float* bq = (const float*)d_in[2];
    const float* Wk = (const float*)d_in[3];
    const float* bk = (const float*)d_in[4];
    const float* Wv = (const float*)d_in[5];
    const float* bv = (const float*)d_in[6];
    const float* Wo = (const float*)d_in[7];
    const float* bo = (const float*)d_in[8];
    float* out = (float*)d_out;

    __half *pq, *pk, *pv, *pao, *pxh, *pwt;
    cudaGetSymbolAddress((void**)&pq,  g_q);
    cudaGetSymbolAddress((void**)&pk,  g_k);
    cudaGetSymbolAddress((void**)&pv,  g_v);
    cudaGetSymbolAddress((void**)&pao, g_ao);
    cudaGetSymbolAddress((void**)&pxh, g_xh);
    cudaGetSymbolAddress((void**)&pwt, g_wt);

    cudaFuncSetAttribute(attn_kernel,
                         cudaFuncAttributeMaxDynamicSharedMemorySize, A_SMEM_B);
    cudaFuncSetAttribute(gemm_qkv_kernel,
                         cudaFuncAttributeMaxDynamicSharedMemorySize, G_SMEM_B);
    cudaFuncSetAttribute(gemm_out_kernel,
                         cudaFuncAttributeMaxDynamicSharedMemorySize, G_SMEM_B);

    prep_kernel<<<dim3(32, 32, 5), 256>>>(x, Wq, Wk, Wv, Wo, pxh, pwt);
    gemm_qkv_kernel<<<dim3(D_MODEL / 256, M_TOTAL / 128, 3), 256, G_SMEM_B>>>(
        pxh, pwt, bq, bk, bv, pq, pk, pv);
    attn_kernel<<<dim3(S_LEN / QT, BATCH * NH), 128, A_SMEM_B>>>(pq, pk, pv, pao);
    gemm_out_kernel<<<dim3(D_MODEL / 256, M_TOTAL / 128), 256, G_SMEM_B>>>(
        pao, pwt, bo, out);
}

// round 16
// speedup vs baseline: 1.1179x; 1.1179x over previous
#include <cuda_runtime.h>
#include <cuda_fp16.h>
#include <cstdint>

#define S_LEN   2048
#define D_MODEL 1024
#define NH      16
#define DKH     64
#define BATCH   2
#define M_TOTAL (BATCH * S_LEN)   // 4096

// fp16 scratch
__device__ __half g_xh[M_TOTAL * D_MODEL];
__device__ __half g_wt[4 * D_MODEL * D_MODEL];   // [z][K][N] fp16 (NO transpose)
__device__ __half g_q [BATCH * NH * S_LEN * DKH];
__device__ __half g_k [BATCH * NH * S_LEN * DKH];
__device__ __half g_v [BATCH * NH * S_LEN * DKH];
__device__ __half g_ao[M_TOTAL * D_MODEL];

__device__ __forceinline__ uint32_t smem_u32(const void* p) {
    uint32_t a;
    asm("{ .reg .u64 t; cvta.to.shared.u64 t, %1; cvt.u32.u64 %0, t; }" : "=r"(a) : "l"(p));
    return a;
}
__device__ __forceinline__ void cp16(uint32_t dst, const void* src) {
    asm volatile("cp.async.cg.shared.global [%0], [%1], 16;" :: "r"(dst), "l"(src));
}
#define CP_COMMIT() asm volatile("cp.async.commit_group;" ::: "memory")
#define CP_WAIT(n)  asm volatile("cp.async.wait_group %0;" :: "n"(n) : "memory")

__device__ __forceinline__ void ldsm4(uint32_t& r0, uint32_t& r1, uint32_t& r2,
                                      uint32_t& r3, uint32_t addr) {
    asm volatile("ldmatrix.sync.aligned.m8n8.x4.shared.b16 {%0,%1,%2,%3}, [%4];"
                 : "=r"(r0), "=r"(r1), "=r"(r2), "=r"(r3) : "r"(addr));
}
__device__ __forceinline__ void ldsm4t(uint32_t& r0, uint32_t& r1, uint32_t& r2,
                                       uint32_t& r3, uint32_t addr) {
    asm volatile("ldmatrix.sync.aligned.m8n8.x4.trans.shared.b16 {%0,%1,%2,%3}, [%4];"
                 : "=r"(r0), "=r"(r1), "=r"(r2), "=r"(r3) : "r"(addr));
}
__device__ __forceinline__ void mma_f16(float c[4], const uint32_t a[4],
                                        uint32_t b0, uint32_t b1) {
    asm volatile(
        "mma.sync.aligned.m16n8k16.row.col.f32.f16.f16.f32 "
        "{%0,%1,%2,%3}, {%4,%5,%6,%7}, {%8,%9}, {%0,%1,%2,%3};"
        : "+f"(c[0]), "+f"(c[1]), "+f"(c[2]), "+f"(c[3])
        : "r"(a[0]), "r"(a[1]), "r"(a[2]), "r"(a[3]), "r"(b0), "r"(b1));
}
__device__ __forceinline__ uint32_t h2pack(float lo, float hi) {
    __half2 h = __floats2half2_rn(lo, hi);
    return *(uint32_t*)&h;
}

// ============================================================================
// Prep: pure streaming fp16 conversion (x and the 4 weights; no transpose).
// ============================================================================
__global__ __launch_bounds__(256)
void prep_kernel(const float* __restrict__ x,
                 const float* __restrict__ Wq, const float* __restrict__ Wk,
                 const float* __restrict__ Wv, const float* __restrict__ Wo,
                 __half* __restrict__ xh, __half* __restrict__ wt) {
    const float* src; __half* dst; int n4;
    const int WN4 = D_MODEL * D_MODEL / 4;
    switch (blockIdx.z) {
        case 0:  src = x;  dst = xh;                          n4 = M_TOTAL * D_MODEL / 4; break;
        case 1:  src = Wq; dst = wt + 0 * D_MODEL * D_MODEL;  n4 = WN4; break;
        case 2:  src = Wk; dst = wt + 1 * D_MODEL * D_MODEL;  n4 = WN4; break;
        case 3:  src = Wv; dst = wt + 2 * D_MODEL * D_MODEL;  n4 = WN4; break;
        default: src = Wo; dst = wt + 3 * D_MODEL * D_MODEL;  n4 = WN4; break;
    }
    int bid = blockIdx.y * gridDim.x + blockIdx.x;
    for (int i = bid * 256 + threadIdx.x; i < n4; i += gridDim.x * gridDim.y * 256) {
        float4 v = ((const float4*)src)[i];
        __half2 h01 = __floats2half2_rn(v.x, v.y);
        __half2 h23 = __floats2half2_rn(v.z, v.w);
        uint2 u = {*(uint32_t*)&h01, *(uint32_t*)&h23};
        ((uint2*)dst)[i] = u;
    }
}

// ============================================================================
// fp16 HMMA GEMM (R12 config, B via ldmatrix.trans from K-major W):
// out[M,N] = (A[M,K] @ W[K,N] + bias) * scale.
// Block 128x128, K-chunk 32, 4 warps (64x64), 128 threads, 2 CTA/SM,
// 4-stage ring, fills 2 ahead, ONE barrier per chunk.
// A stage: 128 rows x GAP32(40) halves. B stage: 32 rows x BP(136) halves
// ([k][n] row-major; ldsm4t row-stride 272B -> offsets 0,16..112 mod 128,
// conflict-free — identical pattern to the attention V path).
// LAYOUT 0: f32 [M,N]; LAYOUT 1: fp16 [B,H,S,dk] scaled.
// ============================================================================
#define GAP32    40
#define BP       136
#define G_STG_B  ((128 * GAP32 + 32 * BP) * 2)   // 10240 + 8704 = 18944 bytes
#define G_NSTG   4
#define G_SMEM_B (G_NSTG * G_STG_B)              // 75776

template <int LAYOUT>
__device__ __forceinline__
void gemm_body(const __half* __restrict__ A, const __half* __restrict__ W,
               const float* __restrict__ bias, void* __restrict__ outv,
               float scale) {
    extern __shared__ char smraw[];
    const uint32_t sb = smem_u32(smraw);
    const int t    = threadIdx.x;
    const int lane = t & 31;
    const int warp = t >> 5;             // 0..3
    const int gid  = lane >> 2;
    const int tig  = lane & 3;
    const int wrow = warp >> 1;          // 0..1
    const int wcol = warp & 1;           // 0..1
    const int m0   = blockIdx.y * 128;
    const int n0   = blockIdx.x * 128;

    float acc[4][8][4];
#pragma unroll
    for (int i = 0; i < 4; i++)
#pragma unroll
        for (int j = 0; j < 8; j++)
#pragma unroll
            for (int k = 0; k < 4; k++) acc[i][j][k] = 0.f;

    auto fill = [&](int chunk, int st) {
        const int kb = chunk * 32;
        const uint32_t ab = sb + st * G_STG_B;
        const uint32_t bb = ab + 128 * GAP32 * 2;
        // A: 128 rows x 32 halves = 512 x 16B, 4 per thread
#pragma unroll
        for (int j = 0; j < 4; j++) {
            int lin = t + j * 128;
            int r = lin >> 2, c8 = (lin & 3) * 8;
            cp16(ab + (r * GAP32 + c8) * 2, &A[(size_t)(m0 + r) * D_MODEL + kb + c8]);
        }
        // B: 32 rows (K) x 128 halves (N) = 512 x 16B, 4 per thread
#pragma unroll
        for (int j = 0; j < 4; j++) {
            int lin = t + j * 128;
            int r = lin >> 4, c8 = (lin & 15) * 8;
            cp16(bb + (r * BP + c8) * 2, &W[(size_t)(kb + r) * D_MODEL + n0 + c8]);
        }
    };

    fill(0, 0); CP_COMMIT();
    fill(1, 1); CP_COMMIT();

    const int a_row8 = (lane & 7) + (((lane & 15) >> 3) << 3);
    const int a_kk8  = (lane >> 4) << 3;
    // B trans addressing (== attention V path): rows = K, cols = N
    const int b_r8 = (lane & 7) + (((lane >> 3) & 1) << 3);
    const int b_c8 = ((lane >> 4) & 1) << 3;

    for (int i = 0; i < 32; i++) {
        if (i + 2 < 32) fill(i + 2, (i + 2) & 3);
        CP_COMMIT();
        CP_WAIT(2);
        __syncthreads();
        const uint32_t ab = sb + (i & 3) * G_STG_B;
        const uint32_t bb = ab + 128 * GAP32 * 2;
#pragma unroll
        for (int kg = 0; kg < 2; kg++) {
            const int kk = kg * 16;
            uint32_t a[4][4];
#pragma unroll
            for (int mt = 0; mt < 4; mt++) {
                int R = wrow * 64 + mt * 16;
                ldsm4(a[mt][0], a[mt][1], a[mt][2], a[mt][3],
                      ab + ((R + a_row8) * GAP32 + kk + a_kk8) * 2);
            }
#pragma unroll
            for (int p = 0; p < 4; p++) {
                int N0 = wcol * 64 + p * 16;
                uint32_t b0, b1, b2, b3;
                ldsm4t(b0, b1, b2, b3,
                       bb + ((kk + b_r8) * BP + N0 + b_c8) * 2);
#pragma unroll
                for (int mt = 0; mt < 4; mt++) {
                    mma_f16(acc[mt][2 * p + 0], a[mt], b0, b1);
                    mma_f16(acc[mt][2 * p + 1], a[mt], b2, b3);
                }
            }
        }
        // no trailing barrier: 4-stage ring keeps writes 2 stages from reads
    }

#pragma unroll
    for (int mt = 0; mt < 4; mt++)
#pragma unroll
        for (int nt = 0; nt < 8; nt++) {
            int c0 = n0 + wcol * 64 + nt * 8 + tig * 2;
            float b0 = bias[c0], b1 = bias[c0 + 1];
#pragma unroll
            for (int h2 = 0; h2 < 2; h2++) {
                int r = m0 + wrow * 64 + mt * 16 + gid + 8 * h2;
                float v0 = acc[mt][nt][2 * h2 + 0] + b0;
                float v1 = acc[mt][nt][2 * h2 + 1] + b1;
                if (LAYOUT == 0) {
                    *(float2*)&((float*)outv)[(size_t)r * D_MODEL + c0] =
                        make_float2(v0, v1);
                } else {
                    int bb2 = r >> 11, ss = r & 2047;
                    int hh = c0 >> 6, dd = c0 & 63;
                    size_t idx = ((size_t)((bb2 * NH + hh) * S_LEN) + ss) * DKH + dd;
                    *(__half2*)&((__half*)outv)[idx] =
                        __floats2half2_rn(v0 * scale, v1 * scale);
                }
            }
        }
}

__global__ __launch_bounds__(128, 2)
void gemm_qkv_kernel(const __half* __restrict__ xh, const __half* __restrict__ wt,
                     const float* __restrict__ bq, const float* __restrict__ bk,
                     const float* __restrict__ bv,
                     __half* __restrict__ oq, __half* __restrict__ ok,
                     __half* __restrict__ ov) {
    const float* b; __half* o; float sc;
    const __half* W = wt + (size_t)blockIdx.z * D_MODEL * D_MODEL;
    if (blockIdx.z == 0)      { b = bq; o = oq; sc = 0.125f; }   // fold 1/sqrt(dk) into Q
    else if (blockIdx.z == 1) { b = bk; o = ok; sc = 1.f; }
    else                      { b = bv; o = ov; sc = 1.f; }
    gemm_body<1>(xh, W, b, o, sc);
}

__global__ __launch_bounds__(128, 2)
void gemm_out_kernel(const __half* __restrict__ A, const __half* __restrict__ wt,
                     const float* __restrict__ bias, float* __restrict__ out) {
    gemm_body<0>(A, wt + (size_t)3 * D_MODEL * D_MODEL, bias, out, 1.f);
}

// ============================================================================
// Flash attention (R12, current best): fp16 HMMA, max-free softmax, Q-tile
// 128, KV-tile 64, 4 warps / 128 threads, warp tile 32x64 (two m-tiles),
// 2 CTAs/SM, 4-stage single-barrier cp.async pipeline.
// ============================================================================
#define QT     128
#define KT     64
#define KVP    72
#define KV_STG (KT * KVP)                 // halves per stage: 4608
#define A_SMEM_B (8 * KV_STG * 2)         // 73728 bytes (4 K + 4 V stages)
#define N_KT   (S_LEN / KT)

__global__ __launch_bounds__(128, 2)
void attn_kernel(const __half* __restrict__ Q, const __half* __restrict__ K,
                 const __half* __restrict__ V, __half* __restrict__ AO) {
    extern __shared__ char smraw[];
    const uint32_t sb  = smem_u32(smraw);
    const uint32_t sbK = sb;
    const uint32_t sbV = sb + 4 * KV_STG * 2;

    const int t    = threadIdx.x;
    const int lane = t & 31;
    const int warp = t >> 5;            // 0..3
    const int gid  = lane >> 2;
    const int tig  = lane & 3;
    const int qt   = blockIdx.x;        // 0..15
    const int bh   = blockIdx.y;        // 0..31
    const int rA   = warp * 32 + gid;   // m-tile 0 rows: rA, rA+8; m-tile 1: +16,+24

    const __half* kg_ = K + (size_t)bh * S_LEN * DKH;
    const __half* vg  = V + (size_t)bh * S_LEN * DKH;

    // Q fragments for both m-tiles, loaded once from global
    uint32_t qf[2][4][4];
#pragma unroll
    for (int mt = 0; mt < 2; mt++) {
        const __half* q0 = Q + ((size_t)bh * S_LEN + qt * QT + rA + 16 * mt) * DKH;
        const __half* q1 = q0 + 8 * DKH;
#pragma unroll
        for (int kg = 0; kg < 4; kg++) {
            qf[mt][kg][0] = *(const uint32_t*)&q0[16 * kg + 2 * tig];
            qf[mt][kg][1] = *(const uint32_t*)&q1[16 * kg + 2 * tig];
            qf[mt][kg][2] = *(const uint32_t*)&q0[16 * kg + 8 + 2 * tig];
            qf[mt][kg][3] = *(const uint32_t*)&q1[16 * kg + 8 + 2 * tig];
        }
    }

    auto fillKV = [&](int kt, int s) {
        const __half* kt_ = kg_ + kt * KT * DKH;
        const __half* vt_ = vg  + kt * KT * DKH;
#pragma unroll
        for (int j = 0; j < 4; j++) {
            int lin = t + j * 128;
            int r = lin >> 3, c8 = (lin & 7) * 8;
            cp16(sbK + s * KV_STG * 2 + (r * KVP + c8) * 2, &kt_[r * DKH + c8]);
            cp16(sbV + s * KV_STG * 2 + (r * KVP + c8) * 2, &vt_[r * DKH + c8]);
        }
    };

    float o[2][8][4];
#pragma unroll
    for (int mt = 0; mt < 2; mt++)
#pragma unroll
        for (int i = 0; i < 8; i++)
#pragma unroll
            for (int j = 0; j < 4; j++) o[mt][i][j] = 0.f;
    float lr[2][2] = {{0.f, 0.f}, {0.f, 0.f}};   // per-thread partial sums

    const int kb_row8 = (lane & 7) + (((lane >> 4) & 1) << 3);
    const int kb_kk8  = ((lane >> 3) & 1) << 3;
    const int vb_row8 = (lane & 7) + (((lane >> 3) & 1) << 3);
    const int vb_cc8  = ((lane >> 4) & 1) << 3;

    fillKV(0, 0); CP_COMMIT();
    fillKV(1, 1); CP_COMMIT();

    for (int kt = 0; kt < N_KT; kt++) {
        if (kt + 2 < N_KT) fillKV(kt + 2, (kt + 2) & 3);
        CP_COMMIT();
        CP_WAIT(2);
        __syncthreads();
        const int st = kt & 3;
        const uint32_t Ks = sbK + st * KV_STG * 2;
        const uint32_t Vs = sbV + st * KV_STG * 2;

        float s[2][8][4];
#pragma unroll
        for (int mt = 0; mt < 2; mt++)
#pragma unroll
            for (int i = 0; i < 8; i++)
#pragma unroll
                for (int j = 0; j < 4; j++) s[mt][i][j] = 0.f;

        // S = Q @ K^T : each K fragment feeds 4 MMAs (2 m-tiles x 2 n-halves)
#pragma unroll
        for (int kg = 0; kg < 4; kg++) {
            const int kk = kg * 16;
#pragma unroll
            for (int p = 0; p < 4; p++) {
                uint32_t b0, b1, b2, b3;
                ldsm4(b0, b1, b2, b3,
                      Ks + ((p * 16 + kb_row8) * KVP + kk + kb_kk8) * 2);
#pragma unroll
                for (int mt = 0; mt < 2; mt++) {
                    mma_f16(s[mt][2 * p + 0], qf[mt][kg], b0, b1);
                    mma_f16(s[mt][2 * p + 1], qf[mt][kg], b2, b3);
                }
            }
        }

        // max-free softmax numerator; accumulate partial denominators
#pragma unroll
        for (int mt = 0; mt < 2; mt++)
#pragma unroll
            for (int nt = 0; nt < 8; nt++) {
                s[mt][nt][0] = __expf(s[mt][nt][0]);
                s[mt][nt][1] = __expf(s[mt][nt][1]);
                s[mt][nt][2] = __expf(s[mt][nt][2]);
                s[mt][nt][3] = __expf(s[mt][nt][3]);
                lr[mt][0] += s[mt][nt][0] + s[mt][nt][1];
                lr[mt][1] += s[mt][nt][2] + s[mt][nt][3];
            }

        // O += P @ V : each V fragment feeds 4 MMAs
#pragma unroll
        for (int kg = 0; kg < 4; kg++) {
            uint32_t pa[2][4];
#pragma unroll
            for (int mt = 0; mt < 2; mt++) {
                pa[mt][0] = h2pack(s[mt][2 * kg][0],     s[mt][2 * kg][1]);
                pa[mt][1] = h2pack(s[mt][2 * kg][2],     s[mt][2 * kg][3]);
                pa[mt][2] = h2pack(s[mt][2 * kg + 1][0], s[mt][2 * kg + 1][1]);
                pa[mt][3] = h2pack(s[mt][2 * kg + 1][2], s[mt][2 * kg + 1][3]);
            }
#pragma unroll
            for (int p = 0; p < 4; p++) {
                uint32_t v0, v1, v2, v3;
                ldsm4t(v0, v1, v2, v3,
                       Vs + ((kg * 16 + vb_row8) * KVP + p * 16 + vb_cc8) * 2);
#pragma unroll
                for (int mt = 0; mt < 2; mt++) {
                    mma_f16(o[mt][2 * p + 0], pa[mt], v0, v1);
                    mma_f16(o[mt][2 * p + 1], pa[mt], v2, v3);
                }
            }
        }
        // no trailing barrier: 4-stage ring
    }

    // reduce denominators across the 4 threads of each row group, write out
    int bb = bh >> 4, hh = bh & 15;
#pragma unroll
    for (int mt = 0; mt < 2; mt++) {
        float l0 = lr[mt][0], l1 = lr[mt][1];
        l0 += __shfl_xor_sync(0xffffffffu, l0, 1);
        l0 += __shfl_xor_sync(0xffffffffu, l0, 2);
        l1 += __shfl_xor_sync(0xffffffffu, l1, 1);
        l1 += __shfl_xor_sync(0xffffffffu, l1, 2);
        float il0 = 1.f / l0, il1 = 1.f / l1;
        int q0 = qt * QT + rA + 16 * mt;
        size_t base0 = ((size_t)(bb * S_LEN + q0)) * D_MODEL + hh * DKH;
        size_t base1 = base0 + (size_t)8 * D_MODEL;
#pragma unroll
        for (int nt = 0; nt < 8; nt++) {
            int dd = nt * 8 + tig * 2;
            *(__half2*)&AO[base0 + dd] =
                __floats2half2_rn(o[mt][nt][0] * il0, o[mt][nt][1] * il0);
            *(__half2*)&AO[base1 + dd] =
                __floats2half2_rn(o[mt][nt][2] * il1, o[mt][nt][3] * il1);
        }
    }
}

// ============================================================================
extern "C" void kernel_launch(void* const* d_in, const int* in_sizes, int n_in,
                              void* d_out, int out_size) {
    (void)in_sizes; (void)n_in; (void)out_size;
    const float* x  = (const float*)d_in[0];
    const float* Wq = (const float*)d_in[1];
    const float* bq = (const float*)d_in[2];
    const float* Wk = (const float*)d_in[3];
    const float* bk = (const float*)d_in[4];
    const float* Wv = (const float*)d_in[5];
    const float* bv = (const float*)d_in[6];
    const float* Wo = (const float*)d_in[7];
    const float* bo = (const float*)d_in[8];
    float* out = (float*)d_out;

    __half *pq, *pk, *pv, *pao, *pxh, *pwt;
    cudaGetSymbolAddress((void**)&pq,  g_q);
    cudaGetSymbolAddress((void**)&pk,  g_k);
    cudaGetSymbolAddress((void**)&pv,  g_v);
    cudaGetSymbolAddress((void**)&pao, g_ao);
    cudaGetSymbolAddress((void**)&pxh, g_xh);
    cudaGetSymbolAddress((void**)&pwt, g_wt);

    cudaFuncSetAttribute(attn_kernel,
                         cudaFuncAttributeMaxDynamicSharedMemorySize, A_SMEM_B);
    cudaFuncSetAttribute(gemm_qkv_kernel,
                         cudaFuncAttributeMaxDynamicSharedMemorySize, G_SMEM_B);
    cudaFuncSetAttribute(gemm_out_kernel,
                         cudaFuncAttributeMaxDynamicSharedMemorySize, G_SMEM_B);

    prep_kernel<<<dim3(32, 32, 5), 256>>>(x, Wq, Wk, Wv, Wo, pxh, pwt);
    gemm_qkv_kernel<<<dim3(8, 32, 3), 128, G_SMEM_B>>>(pxh, pwt, bq, bk, bv,
                                                       pq, pk, pv);
    attn_kernel<<<dim3(S_LEN / QT, BATCH * NH), 128, A_SMEM_B>>>(pq, pk, pv, pao);
    gemm_out_kernel<<<dim3(8, 32), 128, G_SMEM_B>>>(pao, pwt, bo, out);
}